// round 3
// baseline (speedup 1.0000x reference)
#include <cuda_runtime.h>
#include <math.h>

// Problem constants
#define BATCH   2
#define HW      64
#define NPIX    4096
#define BN      8192
#define DIMQ    64
#define CLD     128
#define KTOK    8
#define FLOW_SZ 1048576       // 2*2*512*512

typedef unsigned long long ull;

// Transposed flow-token-encoder weights (filled by upsample blocks 0..23)
__device__ __align__(16) float g_w1t[81 * 64];   // g_w1t[c*64+o] = fte_w1[o*81+c]
__device__ __align__(16) float g_w2t[64 * 64];   // g_w2t[c*64+o] = fte_w2[o*64+c]

__device__ __forceinline__ float gelu_exact(float x) {
    return 0.5f * x * (1.0f + erff(x * 0.70710678118654752f));
}

// ---- packed f32x2 helpers (sm_103a) ----
__device__ __forceinline__ ull ffma2(ull a, ull b, ull c) {
    ull d;
    asm("fma.rn.f32x2 %0, %1, %2, %3;" : "=l"(d) : "l"(a), "l"(b), "l"(c));
    return d;
}
__device__ __forceinline__ ull fadd2(ull a, ull b) {
    ull d;
    asm("add.rn.f32x2 %0, %1, %2;" : "=l"(d) : "l"(a), "l"(b));
    return d;
}
__device__ __forceinline__ float2 u2f(ull a) {
    float2 f;
    asm("mov.b64 {%0, %1}, %2;" : "=f"(f.x), "=f"(f.y) : "l"(a));
    return f;
}

__device__ __forceinline__ float samp_map(const float* __restrict__ p, int ix, int iy) {
    if ((unsigned)ix < 64u && (unsigned)iy < 64u) return p[iy * 64 + ix];
    return 0.0f;
}

struct __align__(16) TokSmem {
    float cm2[2048];    // duplicated cost_memory (m,m) pairs; later k_s[0..511], v_s[512..1023]
    float corr2[176];   // duplicated corr (81 pairs)
    float attn2[128];   // duplicated attn weights (64 pairs)
    float bufA2[128];   // duplicated: q1 -> attn_out -> ffn hidden
    float bufB2[128];   // duplicated: (qn+enc) -> xn
    float short2[128];  // duplicated short
    float qlin[64];     // plain
    float x_s[64];      // plain final
};

__global__ __launch_bounds__(128) void decoder_kernel(
    const float* __restrict__ cost_maps,
    const float* __restrict__ cost_memory,
    const float* __restrict__ coords1,
    const float* __restrict__ fte_b1,
    const float* __restrict__ fte_b2,
    const float* __restrict__ ln1_g, const float* __restrict__ ln1_b,
    const float* __restrict__ ln2_g, const float* __restrict__ ln2_b,
    const float* __restrict__ wq,  const float* __restrict__ bq,
    const float* __restrict__ wk,  const float* __restrict__ bk,
    const float* __restrict__ wv,  const float* __restrict__ bv,
    const float* __restrict__ wp,  const float* __restrict__ bp,
    const float* __restrict__ fw1, const float* __restrict__ fb1,
    const float* __restrict__ fw2, const float* __restrict__ fb2,
    float* __restrict__ out)
{
    __shared__ TokSmem ts[4];
    const int warp = threadIdx.x >> 5;
    const int lane = threadIdx.x & 31;
    const int n    = blockIdx.x * 4 + warp;
    TokSmem& S = ts[warp];

    const int b   = n >> 12;
    const int pix = n & 4095;
    const float cx = coords1[b * 8192 + pix];
    const float cy = coords1[b * 8192 + 4096 + pix];
    const int o0 = 2 * lane, o1 = 2 * lane + 1;

    // ---- load cost_memory tile, duplicated: cm2[2*(j*128+c)] = cm2[..+1] = m ----
    {
        const float4* cm4 = (const float4*)(cost_memory + (size_t)n * 1024);
        float4* c2 = (float4*)S.cm2;
        #pragma unroll
        for (int t = 0; t < 8; ++t) {
            float4 v = cm4[lane + t * 32];
            int e2 = 2 * (lane + t * 32);          // float4 index into cm2
            c2[e2]     = make_float4(v.x, v.x, v.y, v.y);
            c2[e2 + 1] = make_float4(v.z, v.z, v.w, v.w);
        }
    }

    // ---- bilinear correlation sampling (81 samples), duplicated store ----
    {
        const float* cmap = cost_maps + (size_t)n * 4096;
        for (int s = lane; s < 81; s += 32) {
            int si = s / 9, sj = s - si * 9;
            float px = cx + (float)(si - 4);
            float py = cy + (float)(sj - 4);
            float fx0 = floorf(px), fy0 = floorf(py);
            float wx = px - fx0, wy = py - fy0;
            int ix = (int)fx0, iy = (int)fy0;
            float v00 = samp_map(cmap, ix,     iy);
            float v10 = samp_map(cmap, ix + 1, iy);
            float v01 = samp_map(cmap, ix,     iy + 1);
            float v11 = samp_map(cmap, ix + 1, iy + 1);
            float val = v00 * (1.f - wx) * (1.f - wy) + v10 * wx * (1.f - wy)
                      + v01 * (1.f - wx) * wy         + v11 * wx * wy;
            ((float2*)S.corr2)[s] = make_float2(val, val);
        }
    }
    __syncwarp();

    // ---- flow token encoder stage 1: gelu(W1 @ corr + b1) ----
    {
        ull acc = *(const ull*)(fte_b1 + o0);
        #pragma unroll 3
        for (int c = 0; c < 81; ++c) {
            ull m2 = *(const ull*)(&S.corr2[2 * c]);
            ull w2 = *(const ull*)(&g_w1t[c * 64 + o0]);
            acc = ffma2(m2, w2, acc);
        }
        float2 g = u2f(acc);
        g.x = gelu_exact(g.x); g.y = gelu_exact(g.y);
        ((float4*)S.bufA2)[lane] = make_float4(g.x, g.x, g.y, g.y);
    }
    __syncwarp();

    // ---- stage 2: query = W2 @ q1 + b2 (= short) ----
    float q0, q1v;
    {
        ull acc = *(const ull*)(fte_b2 + o0);
        #pragma unroll 4
        for (int c = 0; c < 64; c += 2) {
            longlong2 m = *(const longlong2*)(&S.bufA2[2 * c]);
            acc = ffma2((ull)m.x, *(const ull*)(&g_w2t[c * 64 + o0]), acc);
            acc = ffma2((ull)m.y, *(const ull*)(&g_w2t[(c + 1) * 64 + o0]), acc);
        }
        float2 qf = u2f(acc);
        q0 = qf.x; q1v = qf.y;
        ((float4*)S.short2)[lane] = make_float4(q0, q0, q1v, q1v);
    }

    // ---- layernorm1 + positional encoding ----
    {
        float sm = q0 + q1v;
        #pragma unroll
        for (int off = 16; off; off >>= 1) sm += __shfl_xor_sync(0xffffffffu, sm, off);
        float mean = sm * (1.0f / 64.0f);
        float d0 = q0 - mean, d1 = q1v - mean;
        float vs = d0 * d0 + d1 * d1;
        #pragma unroll
        for (int off = 16; off; off >>= 1) vs += __shfl_xor_sync(0xffffffffu, vs, off);
        float inv = rsqrtf(vs * (1.0f / 64.0f) + 1e-5f);

        float enc0, enc1;
        {
            int r = o0 >> 4, f = o0 & 15;
            float base = (r < 2) ? cx : cy;
            float ang = 3.14f * base * (float)f / 200.0f;
            enc0 = ((r & 1) == 0) ? sinf(ang) : cosf(ang);
        }
        {
            int r = o1 >> 4, f = o1 & 15;
            float base = (r < 2) ? cx : cy;
            float ang = 3.14f * base * (float)f / 200.0f;
            enc1 = ((r & 1) == 0) ? sinf(ang) : cosf(ang);
        }
        float v0 = d0 * inv * ln1_g[o0] + ln1_b[o0] + enc0;
        float v1 = d1 * inv * ln1_g[o1] + ln1_b[o1] + enc1;
        ((float4*)S.bufB2)[lane] = make_float4(v0, v0, v1, v1);
    }
    __syncwarp();

    // ---- q projection ----
    {
        ull acc = *(const ull*)(bq + o0);
        #pragma unroll 4
        for (int i = 0; i < 64; i += 2) {
            longlong2 m = *(const longlong2*)(&S.bufB2[2 * i]);
            acc = ffma2((ull)m.x, *(const ull*)(&wq[i * 64 + o0]), acc);
            acc = ffma2((ull)m.y, *(const ull*)(&wq[(i + 1) * 64 + o0]), acc);
        }
        ((float2*)S.qlin)[lane] = u2f(acc);
    }

    // ---- K/V projections (FLOP hotspot): 2048 FFMA2/lane ----
    ull kacc[8], vacc[8];
    #pragma unroll
    for (int j = 0; j < 8; ++j) { kacc[j] = 0ull; vacc[j] = 0ull; }
    #pragma unroll 2
    for (int c = 0; c < 128; c += 2) {
        ull wka = *(const ull*)(&wk[c * 64 + o0]);
        ull wkb = *(const ull*)(&wk[(c + 1) * 64 + o0]);
        ull wva = *(const ull*)(&wv[c * 64 + o0]);
        ull wvb = *(const ull*)(&wv[(c + 1) * 64 + o0]);
        #pragma unroll
        for (int j = 0; j < 8; ++j) {
            longlong2 m = *(const longlong2*)(&S.cm2[j * 256 + 2 * c]);
            kacc[j] = ffma2((ull)m.x, wka, kacc[j]);
            kacc[j] = ffma2((ull)m.y, wkb, kacc[j]);
            vacc[j] = ffma2((ull)m.x, wva, vacc[j]);
            vacc[j] = ffma2((ull)m.y, wvb, vacc[j]);
        }
    }
    __syncwarp();   // all lanes done reading cm2; reuse as k_s/v_s
    {
        ull bk2 = *(const ull*)(bk + o0);
        ull bv2 = *(const ull*)(bv + o0);
        float2* k2 = (float2*)S.cm2;
        float2* v2 = (float2*)(S.cm2 + 512);
        #pragma unroll
        for (int j = 0; j < 8; ++j) {
            k2[j * 32 + lane] = u2f(fadd2(kacc[j], bk2));
            v2[j * 32 + lane] = u2f(fadd2(vacc[j], bv2));
        }
    }
    __syncwarp();

    // ---- attention scores + softmax: heads=8, hd=8, K=8 ----
    {
        const float* k_s = S.cm2;
        int h0 = lane >> 3, jj = lane & 7;
        int h1 = h0 + 4;
        float s0 = 0.f, s1 = 0.f;
        #pragma unroll
        for (int d = 0; d < 8; ++d) {
            s0 = fmaf(S.qlin[h0 * 8 + d], k_s[jj * 64 + h0 * 8 + d], s0);
            s1 = fmaf(S.qlin[h1 * 8 + d], k_s[jj * 64 + h1 * 8 + d], s1);
        }
        s0 *= 0.35355339059327373f;
        s1 *= 0.35355339059327373f;
        float m0 = s0, m1 = s1;
        #pragma unroll
        for (int off = 4; off; off >>= 1) {
            m0 = fmaxf(m0, __shfl_xor_sync(0xffffffffu, m0, off));
            m1 = fmaxf(m1, __shfl_xor_sync(0xffffffffu, m1, off));
        }
        float e0 = expf(s0 - m0), e1 = expf(s1 - m1);
        float t0 = e0, t1 = e1;
        #pragma unroll
        for (int off = 4; off; off >>= 1) {
            t0 += __shfl_xor_sync(0xffffffffu, t0, off);
            t1 += __shfl_xor_sync(0xffffffffu, t1, off);
        }
        float w0 = e0 / t0, w1 = e1 / t1;
        ((float2*)S.attn2)[h0 * 8 + jj] = make_float2(w0, w0);
        ((float2*)S.attn2)[h1 * 8 + jj] = make_float2(w1, w1);
    }
    __syncwarp();

    // ---- attn @ V ----
    {
        int h = lane >> 2;   // head of both o0 and o1 (o0 even)
        ull acc = 0ull;
        #pragma unroll
        for (int j = 0; j < 8; ++j) {
            ull w2 = *(const ull*)(&S.attn2[2 * (h * 8 + j)]);
            ull vp = *(const ull*)(&S.cm2[512 + j * 64 + o0]);
            acc = ffma2(w2, vp, acc);
        }
        float2 ao = u2f(acc);
        ((float4*)S.bufA2)[lane] = make_float4(ao.x, ao.x, ao.y, ao.y);
    }
    __syncwarp();

    // ---- proj: x = concat(out, short) @ wp + bp + short ----
    float x0, x1;
    {
        ull acc = *(const ull*)(bp + o0);
        #pragma unroll 4
        for (int i = 0; i < 64; i += 2) {
            longlong2 m = *(const longlong2*)(&S.bufA2[2 * i]);
            acc = ffma2((ull)m.x, *(const ull*)(&wp[i * 64 + o0]), acc);
            acc = ffma2((ull)m.y, *(const ull*)(&wp[(i + 1) * 64 + o0]), acc);
        }
        #pragma unroll 4
        for (int i = 0; i < 64; i += 2) {
            longlong2 m = *(const longlong2*)(&S.short2[2 * i]);
            acc = ffma2((ull)m.x, *(const ull*)(&wp[(64 + i) * 64 + o0]), acc);
            acc = ffma2((ull)m.y, *(const ull*)(&wp[(64 + i + 1) * 64 + o0]), acc);
        }
        float2 xf = u2f(acc);
        x0 = xf.x + S.short2[4 * lane];
        x1 = xf.y + S.short2[4 * lane + 2];
    }

    // ---- layernorm2 ----
    {
        float sm = x0 + x1;
        #pragma unroll
        for (int off = 16; off; off >>= 1) sm += __shfl_xor_sync(0xffffffffu, sm, off);
        float mean = sm * (1.0f / 64.0f);
        float d0 = x0 - mean, d1 = x1 - mean;
        float vs = d0 * d0 + d1 * d1;
        #pragma unroll
        for (int off = 16; off; off >>= 1) vs += __shfl_xor_sync(0xffffffffu, vs, off);
        float inv = rsqrtf(vs * (1.0f / 64.0f) + 1e-5f);
        float v0 = d0 * inv * ln2_g[o0] + ln2_b[o0];
        float v1 = d1 * inv * ln2_g[o1] + ln2_b[o1];
        ((float4*)S.bufB2)[lane] = make_float4(v0, v0, v1, v1);
    }
    __syncwarp();

    // ---- FFN hidden ----
    {
        ull acc = *(const ull*)(fb1 + o0);
        #pragma unroll 4
        for (int i = 0; i < 64; i += 2) {
            longlong2 m = *(const longlong2*)(&S.bufB2[2 * i]);
            acc = ffma2((ull)m.x, *(const ull*)(&fw1[i * 64 + o0]), acc);
            acc = ffma2((ull)m.y, *(const ull*)(&fw1[(i + 1) * 64 + o0]), acc);
        }
        float2 g = u2f(acc);
        g.x = gelu_exact(g.x); g.y = gelu_exact(g.y);
        ((float4*)S.bufA2)[lane] = make_float4(g.x, g.x, g.y, g.y);
    }
    __syncwarp();

    // ---- FFN out + residual ----
    {
        ull acc = *(const ull*)(fb2 + o0);
        #pragma unroll 4
        for (int i = 0; i < 64; i += 2) {
            longlong2 m = *(const longlong2*)(&S.bufA2[2 * i]);
            acc = ffma2((ull)m.x, *(const ull*)(&fw2[i * 64 + o0]), acc);
            acc = ffma2((ull)m.y, *(const ull*)(&fw2[(i + 1) * 64 + o0]), acc);
        }
        float2 f = u2f(acc);
        ((float2*)S.x_s)[lane] = make_float2(x0 + f.x, x1 + f.y);
    }

    // ---- block-staged transposed writeout ----
    __syncthreads();
    {
        int n0 = blockIdx.x * 4;
        int bb = n0 >> 12;
        int pix0 = n0 & 4095;
        float* cg = out + FLOW_SZ + (size_t)bb * 64 * 4096;
        for (int idx = threadIdx.x; idx < 256; idx += 128) {
            int o = idx >> 2, t = idx & 3;
            cg[o * 4096 + pix0 + t] = ts[t].x_s[o];
        }
    }
}

// Convex upsampling; blocks 0..23 additionally transpose the FTE weights.
__global__ __launch_bounds__(256) void upsample_kernel(
    const float* __restrict__ coords1,
    const float* __restrict__ up_mask,
    const float* __restrict__ fte_w1,
    const float* __restrict__ fte_w2,
    float* __restrict__ out)
{
    __shared__ float slab[576 * 8];
    __shared__ float fl[2][3][10];
    __shared__ float outp[2 * 8 * 64];

    int blk = blockIdx.x;
    int tid = threadIdx.x;

    if (blk < 24) {
        int i = blk * 256 + tid;
        if (i < 81 * 64) {
            int c = i >> 6, o = i & 63;
            g_w1t[i] = fte_w1[o * 81 + c];
        }
        if (i < 64 * 64) {
            int c = i >> 6, o = i & 63;
            g_w2t[i] = fte_w2[o * 64 + c];
        }
    }

    int b   = blk >> 9;
    int rem = blk & 511;
    int y   = rem >> 3;
    int x0  = (rem & 7) << 3;

    const float* mbase = up_mask + (size_t)b * 576 * 4096 + y * 64 + x0;
    for (int idx = tid; idx < 576 * 8; idx += 256) {
        int ch = idx >> 3, p = idx & 7;
        slab[idx] = mbase[(size_t)ch * 4096 + p];
    }
    if (tid < 60) {
        int c = tid / 30, r2 = tid % 30, r = r2 / 10, cc = r2 % 10;
        int yy = y + r - 1, xx = x0 + cc - 1;
        float v = 0.0f;
        if ((unsigned)yy < 64u && (unsigned)xx < 64u) {
            float coord = coords1[b * 8192 + c * 4096 + yy * 64 + xx];
            v = 8.0f * (coord - (float)(c == 0 ? xx : yy));
        }
        fl[c][r][cc] = v;
    }
    __syncthreads();

    for (int q = tid; q < 512; q += 256) {
        int p  = q & 7;
        int ij = q >> 3;
        int i  = ij >> 3, j = ij & 7;
        float w[9];
        float mx = -1e30f;
        #pragma unroll
        for (int kk = 0; kk < 9; ++kk) {
            w[kk] = slab[(kk * 64 + ij) * 8 + p];
            mx = fmaxf(mx, w[kk]);
        }
        float s = 0.f;
        #pragma unroll
        for (int kk = 0; kk < 9; ++kk) { w[kk] = __expf(w[kk] - mx); s += w[kk]; }
        float inv = 1.0f / s;
        float u0 = 0.f, u1 = 0.f;
        #pragma unroll
        for (int kk = 0; kk < 9; ++kk) {
            int dy = kk / 3, dx = kk - dy * 3;
            u0 = fmaf(w[kk], fl[0][dy][p + dx], u0);
            u1 = fmaf(w[kk], fl[1][dy][p + dx], u1);
        }
        int col = p * 8 + j;
        outp[(0 * 8 + i) * 64 + col] = u0 * inv;
        outp[(1 * 8 + i) * 64 + col] = u1 * inv;
    }
    __syncthreads();

    float* obase = out + (size_t)b * 2 * 512 * 512 + (size_t)(8 * y) * 512 + 8 * x0;
    for (int idx = tid; idx < 1024; idx += 256) {
        int c = idx >> 9, rest = idx & 511;
        int i = rest >> 6, col = rest & 63;
        obase[(size_t)c * 512 * 512 + i * 512 + col] = outp[(c * 8 + i) * 64 + col];
    }
}

extern "C" void kernel_launch(void* const* d_in, const int* in_sizes, int n_in,
                              void* d_out, int out_size) {
    const float* cost_maps   = (const float*)d_in[0];
    const float* cost_memory = (const float*)d_in[1];
    const float* coords1     = (const float*)d_in[2];
    const float* up_mask     = (const float*)d_in[3];
    const float* fte_w1      = (const float*)d_in[4];
    const float* fte_b1      = (const float*)d_in[5];
    const float* fte_w2      = (const float*)d_in[6];
    const float* fte_b2      = (const float*)d_in[7];
    const float* ln1_g       = (const float*)d_in[8];
    const float* ln1_b       = (const float*)d_in[9];
    const float* ln2_g       = (const float*)d_in[10];
    const float* ln2_b       = (const float*)d_in[11];
    const float* wq          = (const float*)d_in[12];
    const float* bq          = (const float*)d_in[13];
    const float* wk          = (const float*)d_in[14];
    const float* bk          = (const float*)d_in[15];
    const float* wv          = (const float*)d_in[16];
    const float* bv          = (const float*)d_in[17];
    const float* wp          = (const float*)d_in[18];
    const float* bp          = (const float*)d_in[19];
    const float* fw1         = (const float*)d_in[20];
    const float* fb1         = (const float*)d_in[21];
    const float* fw2         = (const float*)d_in[22];
    const float* fb2         = (const float*)d_in[23];
    float* out = (float*)d_out;

    upsample_kernel<<<1024, 256>>>(coords1, up_mask, fte_w1, fte_w2, out);
    decoder_kernel<<<2048, 128>>>(cost_maps, cost_memory, coords1,
                                  fte_b1, fte_b2,
                                  ln1_g, ln1_b, ln2_g, ln2_b,
                                  wq, bq, wk, bk, wv, bv, wp, bp,
                                  fw1, fb1, fw2, fb2, out);
}